// round 14
// baseline (speedup 1.0000x reference)
#include <cuda_runtime.h>
#include <cuda_fp16.h>
#include <cstdint>
#include <math.h>

#define S_LEN  128
#define D_DIM  25
#define NCLS   5
#define E_DIM  301
#define KSEG   320                 // padded K per segment (301 -> 320)
#define MROWS  50048               // vocab padded to 128
#define NPAD   640                 // GEMM covers table cols [0,640): 5 full tiles
#define KBIG   960                 // 3 segments
#define PSTR   672                 // Ptable row stride (floats)
#define VOCAB_MAX 50000
#define BM     128
#define BN     128
#define BK     64
#define NCHUNK 15                  // 960/64
#define PLANE  ((size_t)MROWS * KSEG)
#define RSCALE 2048.0f             // residual-plane scale (2^11)
#define BBLK   800                 // prep blocks doing the B split (640*320/256)

// Segment order (correction first, main last):
//   chunks 0-4:   a0   x b1'   (B offset 0)    -> acc (at 2048x)
//   chunks 5-9:   a1'  x b0    (B offset 320)  -> acc (at 2048x)
//   [acc *= 1/2048]
//   chunks 10-14: a0   x b0    (B offset 640)  -> acc
// Table cols 640-649 (linear, W cols 15-24): fp32 exact, computed by tail_kernel
// on a side stream CONCURRENTLY with the GEMM (joined before the recurrence).

// ---------------- device globals (no runtime alloc allowed) ----------------
__device__ __align__(16) float  g_Ptable[(size_t)VOCAB_MAX * PSTR];
__device__ __align__(16) __half g_Ah[2 * PLANE];                // planes: a0, a1*2048
__device__ __align__(16) __half g_Bh[(size_t)NPAD * KBIG];      // rows: [b1*2048 | b0 | b0]

// ---------------- helpers ----------------
__device__ __forceinline__ uint32_t smem_u32(const void* p) {
    uint32_t a;
    asm("{ .reg .u64 t; cvta.to.shared.u64 t, %1; cvt.u32.u64 %0, t; }" : "=r"(a) : "l"(p));
    return a;
}
// 16B-granular xor swizzle for 128B rows
#define SWZ(row, cg) ((((uint32_t)(row)) << 7) + ((((cg) ^ ((row) & 7))) << 4))

#define CP16(dst, src) asm volatile("cp.async.cg.shared.global [%0], [%1], 16;" :: "r"(dst), "l"(src))
#define CP_COMMIT()    asm volatile("cp.async.commit_group;" ::: "memory")
#define CP_WAIT1()     asm volatile("cp.async.wait_group 1;" ::: "memory")

#define LDSM4(r, a) asm volatile( \
    "ldmatrix.sync.aligned.m8n8.x4.shared.b16 {%0,%1,%2,%3}, [%4];" \
    : "=r"((r)[0]), "=r"((r)[1]), "=r"((r)[2]), "=r"((r)[3]) : "r"(a))

#define MMA16816(c, a, b0, b1) asm volatile( \
    "mma.sync.aligned.m16n8k16.row.col.f32.f16.f16.f32 " \
    "{%0,%1,%2,%3}, {%4,%5,%6,%7}, {%8,%9}, {%0,%1,%2,%3};" \
    : "+f"((c)[0]), "+f"((c)[1]), "+f"((c)[2]), "+f"((c)[3]) \
    : "r"((a)[0]), "r"((a)[1]), "r"((a)[2]), "r"((a)[3]), "r"(b0), "r"(b1))

// ---------------------------------------------------------------------------
// prep_AB: blocks [0,BBLK) build B planes; blocks [BBLK,..) split emb rows
// into fp16 planes a0 / a1*2048 (half2 stores). No tail work here.
// ---------------------------------------------------------------------------
__global__ void __launch_bounds__(256)
prep_AB(const float* __restrict__ emb, const float* __restrict__ A,
        const float* __restrict__ W, int vocab)
{
    if (blockIdx.x < BBLK) {
        // ---- B split: rows [n][960]: [0,320): b1*2048, [320,640): b0, [640,960): b0
        int idx = blockIdx.x * 256 + threadIdx.x;
        if (idx >= NPAD * KSEG) return;
        int n = idx / KSEG, k = idx % KSEG;
        float v = 0.f;
        if (k < E_DIM) {
            if (n < 625) v = A[((size_t)(n / 25) * E_DIM + k) * 25 + (n % 25)];
            else         v = W[(size_t)k * 25 + (n - 625)];
        }
        __half b0 = __float2half_rn(v);
        float r = (v - __half2float(b0)) * RSCALE;
        __half* row = g_Bh + (size_t)n * KBIG;
        row[k]       = __float2half_rn(r);
        row[320 + k] = b0;
        row[640 + k] = b0;
        return;
    }

    // ---- A split (one warp per vocab row) ----
    const int lane = threadIdx.x & 31;
    const int m = (blockIdx.x - BBLK) * 8 + (threadIdx.x >> 5);
    if (m >= MROWS) return;
    const bool live = (m < vocab);
    const float* xr = emb + (size_t)m * E_DIM;
    __half2* p0 = (__half2*)(g_Ah + (size_t)m * KSEG);
    __half2* p1 = (__half2*)(g_Ah + PLANE + (size_t)m * KSEG);

    #pragma unroll
    for (int i = 0; i < 5; ++i) {
        const int h = lane + 32 * i;        // half2 index, e = 2h
        const int e = 2 * h;
        float x0 = (live && e     < E_DIM) ? xr[e]     : 0.f;
        float x1 = (live && e + 1 < E_DIM) ? xr[e + 1] : 0.f;
        __half a00 = __float2half_rn(x0);
        __half a01 = __float2half_rn(x1);
        float r0 = (x0 - __half2float(a00)) * RSCALE;
        float r1 = (x1 - __half2float(a01)) * RSCALE;
        p0[h] = __halves2half2(a00, a01);
        p1[h] = __halves2half2(__float2half_rn(r0), __float2half_rn(r1));
    }
}

// ---------------------------------------------------------------------------
// tail_kernel: table cols 640-649 = emb . W[:,15..24] + b[15..24] (fp32 exact).
// One warp per vocab row. Runs on a SIDE STREAM concurrently with the GEMM
// (it writes Ptable cols the GEMM never touches; joined before recurrence).
// ---------------------------------------------------------------------------
__global__ void __launch_bounds__(256)
tail_kernel(const float* __restrict__ emb, const float* __restrict__ W,
            const float* __restrict__ bvec, int vocab)
{
    __shared__ float Wt[E_DIM][10];
    for (int i = threadIdx.x; i < E_DIM * 10; i += 256) {
        int e = i / 10, d = i % 10;
        Wt[e][d] = W[e * 25 + 15 + d];
    }
    __syncthreads();

    const int lane = threadIdx.x & 31;
    const int m = blockIdx.x * 8 + (threadIdx.x >> 5);
    if (m >= vocab) return;
    const float* xr = emb + (size_t)m * E_DIM;

    float acc[10];
    #pragma unroll
    for (int d = 0; d < 10; ++d) acc[d] = 0.f;
    for (int e = lane; e < E_DIM; e += 32) {
        float x = xr[e];
        #pragma unroll
        for (int d = 0; d < 10; ++d) acc[d] = fmaf(x, Wt[e][d], acc[d]);
    }
    #pragma unroll
    for (int d = 0; d < 10; ++d)
        #pragma unroll
        for (int o = 16; o; o >>= 1)
            acc[d] += __shfl_down_sync(0xffffffffu, acc[d], o);
    if (lane == 0) {
        float* orow = g_Ptable + (size_t)m * PSTR;
        #pragma unroll
        for (int d = 0; d < 10; ++d) orow[640 + d] = acc[d] + bvec[15 + d];
    }
}

// ---------------------------------------------------------------------------
// HMMA GEMM: 512 threads, 16 warps (4m x 4n grid), warp tile 32x32.
// 8 warps/SMSP for latency hiding. 3-stage cp.async multistage,
// single barrier per chunk. CTA tile 128x128, BK=64.  (Unchanged from R12.)
// ---------------------------------------------------------------------------
#define SM_STAGE 32768
#define SM_ADDV  (3 * SM_STAGE)
#define SM_TOTAL (3 * SM_STAGE + 512)

__global__ void __launch_bounds__(512, 2)
gemm_hmma(const float* __restrict__ V, const float* __restrict__ bvec, int vocab)
{
    extern __shared__ __align__(128) char smem[];
    const uint32_t sbase = smem_u32(smem);
    float* addv = (float*)(smem + SM_ADDV);

    const int tid  = threadIdx.x;
    const int w    = tid >> 5, lane = tid & 31;
    const int m0   = blockIdx.y * BM;
    const int n0   = blockIdx.x * BN;

    if (tid < BN) {
        int n = n0 + tid;
        float a;
        if (n < 625) a = V[(n % 25) * 25 + (n / 25)];
        else         a = bvec[n - 625];
        addv[tid] = a;
    }

    // ---- cp.async mapping: 512 threads, each 2x16B in A and B per chunk
    const int lrow = tid >> 2;
    const int lcg0 = (tid & 3) * 2;
    const uint32_t swz0 = SWZ(lrow, lcg0), swz1 = SWZ(lrow, lcg0 + 1);
    const __half* a_base = g_Ah + (size_t)(m0 + lrow) * KSEG + lcg0 * 8;
    const __half* b_base = g_Bh + (size_t)(n0 + lrow) * KBIG + lcg0 * 8;

    auto load_chunk = [&](int c, int st) {
        const int koff = (c % 5) * BK;
        const __half* asrc = a_base + ((c >= 5 && c < 10) ? PLANE : 0) + koff;
        const __half* bsrc = b_base + ((c < 5) ? 0 : ((c < 10) ? 320 : 640)) + koff;
        const uint32_t abase = sbase + st * SM_STAGE;
        const uint32_t bbase = abase + 16384;
        CP16(abase + swz0, asrc);
        CP16(abase + swz1, asrc + 8);
        CP16(bbase + swz0, bsrc);
        CP16(bbase + swz1, bsrc + 8);
    };

    float acc[2][4][4];
    #pragma unroll
    for (int mi = 0; mi < 2; ++mi)
        #pragma unroll
        for (int nj = 0; nj < 4; ++nj)
            #pragma unroll
            for (int q = 0; q < 4; ++q) acc[mi][nj][q] = 0.f;

    const int rowa = (w & 3) * 32 + (lane & 15);
    const int rowb = (w >> 2) * 32 + (lane & 15);
    const int cgl  = lane >> 4;

    load_chunk(0, 0); CP_COMMIT();
    load_chunk(1, 1); CP_COMMIT();

    #pragma unroll 3
    for (int c = 0; c < NCHUNK; ++c) {
        const int st = c % 3;
        CP_WAIT1();                     // group c complete (c+1 may be in flight)
        __syncthreads();                // all warps done reading stage (c+2)%3
        if (c + 2 < NCHUNK) {           // issue loads early, overlap with compute
            load_chunk(c + 2, (c + 2) % 3);
            CP_COMMIT();
        }
        if (c == 10) {
            const float inv = 1.0f / RSCALE;
            #pragma unroll
            for (int mi = 0; mi < 2; ++mi)
                #pragma unroll
                for (int nj = 0; nj < 4; ++nj)
                    #pragma unroll
                    for (int q = 0; q < 4; ++q) acc[mi][nj][q] *= inv;
        }
        const uint32_t abase = sbase + st * SM_STAGE;
        const uint32_t bbase = abase + 16384;

        uint32_t af2[2][2][4], bf2[2][2][4];
        LDSM4(af2[0][0], abase + SWZ(rowa,      cgl));
        LDSM4(af2[0][1], abase + SWZ(rowa + 16, cgl));
        LDSM4(bf2[0][0], bbase + SWZ(rowb,      cgl));
        LDSM4(bf2[0][1], bbase + SWZ(rowb + 16, cgl));

        #pragma unroll
        for (int kt = 0; kt < 4; ++kt) {
            const int cur = kt & 1;
            if (kt < 3) {               // prefetch next kt's fragments
                const int cgn = 2 * kt + 2 + cgl;
                LDSM4(af2[cur ^ 1][0], abase + SWZ(rowa,      cgn));
                LDSM4(af2[cur ^ 1][1], abase + SWZ(rowa + 16, cgn));
                LDSM4(bf2[cur ^ 1][0], bbase + SWZ(rowb,      cgn));
                LDSM4(bf2[cur ^ 1][1], bbase + SWZ(rowb + 16, cgn));
            }
            #pragma unroll
            for (int mi = 0; mi < 2; ++mi)
                #pragma unroll
                for (int n8 = 0; n8 < 4; ++n8)
                    MMA16816(acc[mi][n8], af2[cur][mi],
                             bf2[cur][n8 >> 1][n8 & 1], bf2[cur][n8 >> 1][2 + (n8 & 1)]);
        }
    }

    // ---- epilogue: add fold values, store float2 pairs ----
    #pragma unroll
    for (int mi = 0; mi < 2; ++mi) {
        const int r0 = m0 + (w & 3) * 32 + mi * 16 + (lane >> 2);
        #pragma unroll
        for (int n8 = 0; n8 < 4; ++n8) {
            const int ln = (w >> 2) * 32 + n8 * 8 + (lane & 3) * 2;
            const int n  = n0 + ln;
            const float a0 = addv[ln], a1 = addv[ln + 1];
            if (r0 < vocab) {
                float2 v; v.x = acc[mi][n8][0] + a0; v.y = acc[mi][n8][1] + a1;
                *(float2*)(g_Ptable + (size_t)r0 * PSTR + n) = v;
            }
            if (r0 + 8 < vocab) {
                float2 v; v.x = acc[mi][n8][2] + a0; v.y = acc[mi][n8][3] + a1;
                *(float2*)(g_Ptable + (size_t)(r0 + 8) * PSTR + n) = v;
            }
        }
    }
}

// ---------------------------------------------------------------------------
// Recurrence (74us, LTS-bound floor): warp per batch element,
// cp.async 3-buffer pipeline. h_new = tanh(c + P h); fused sigmoid head.
// ---------------------------------------------------------------------------
#define WPB 4
__global__ void __launch_bounds__(128)
recurrence_kernel(const int* __restrict__ words,
                  const float* __restrict__ outW,
                  const float* __restrict__ outb,
                  float* __restrict__ out,
                  int B)
{
    __shared__ __align__(16) float Pbuf[WPB][3][656];
    __shared__ float hs[WPB][32];

    const int lane = threadIdx.x & 31;
    const int w    = threadIdx.x >> 5;
    const int b    = blockIdx.x * WPB + w;
    if (b >= B) return;   // uniform per warp

    const int* wrow = words + (size_t)b * S_LEN;
    float* hb = hs[w];
    hb[lane] = (lane == D_DIM - 1) ? 1.f : 0.f;

    auto issue = [&](int t, int s) {
        const char* src = (const char*)(g_Ptable + (size_t)wrow[t] * PSTR);
        const uint32_t dst = smem_u32(&Pbuf[w][s][0]);
        #pragma unroll
        for (int i = 0; i < 6; ++i) {
            int q = lane + 32 * i;
            if (q < 164) CP16(dst + q * 16, src + q * 16);
        }
    };

    issue(0, 0); CP_COMMIT();
    issue(1, 1); CP_COMMIT();

    for (int t = 0; t < S_LEN; ++t) {
        CP_WAIT1();
        __syncwarp();
        const float* pc = Pbuf[w][t % 3];
        float hn = 0.f;
        if (lane < D_DIM) {
            float acc = pc[625 + lane];
            const float* prow = pc + lane * D_DIM;
            #pragma unroll
            for (int j = 0; j < D_DIM; ++j)
                acc = fmaf(prow[j], hb[j], acc);
            hn = tanhf(acc);
        }
        __syncwarp();
        if (lane < D_DIM) hb[lane] = hn;
        __syncwarp();
        if (t + 2 < S_LEN) issue(t + 2, (t + 2) % 3);
        CP_COMMIT();
    }

    if (lane < NCLS) {
        float acc = outb[lane];
        #pragma unroll
        for (int i = 0; i < D_DIM; ++i)
            acc = fmaf(outW[lane * D_DIM + i], hb[i], acc);
        out[(size_t)b * NCLS + lane] = 1.f / (1.f + expf(-acc));
    }
}

// ---------------------------------------------------------------------------
extern "C" void kernel_launch(void* const* d_in, const int* in_sizes, int n_in,
                              void* d_out, int out_size)
{
    // inputs: words, [batch_size], emb_table, A, W, V, b, out_W, out_b
    const int o = (n_in >= 9) ? 1 : 0;
    const int*   words = (const int*)  d_in[0];
    const float* emb   = (const float*)d_in[1 + o];
    const float* A     = (const float*)d_in[2 + o];
    const float* W     = (const float*)d_in[3 + o];
    const float* V     = (const float*)d_in[4 + o];
    const float* bvec  = (const float*)d_in[5 + o];
    const float* outW  = (const float*)d_in[6 + o];
    const float* outb  = (const float*)d_in[7 + o];
    float* out = (float*)d_out;

    const int B = in_sizes[0] / S_LEN;
    int vocab   = in_sizes[1 + o] / E_DIM;
    if (vocab > VOCAB_MAX) vocab = VOCAB_MAX;

    // one-time host-side setup (no device memory involved)
    static cudaStream_t s2 = nullptr;
    static cudaEvent_t evFork = nullptr, evJoin = nullptr;
    if (!s2) {
        cudaStreamCreateWithFlags(&s2, cudaStreamNonBlocking);
        cudaEventCreateWithFlags(&evFork, cudaEventDisableTiming);
        cudaEventCreateWithFlags(&evJoin, cudaEventDisableTiming);
        cudaFuncSetAttribute(gemm_hmma, cudaFuncAttributeMaxDynamicSharedMemorySize, SM_TOTAL);
    }

    // fork: fp32 tail (Ptable cols 640-649) on side stream, parallel with GEMM
    cudaEventRecord(evFork, 0);
    cudaStreamWaitEvent(s2, evFork, 0);
    tail_kernel<<<(vocab + 7) / 8, 256, 0, s2>>>(emb, W, bvec, vocab);
    cudaEventRecord(evJoin, s2);

    // main stream: prep A/B planes, then GEMM -> table cols [0,640)
    prep_AB<<<BBLK + MROWS / 8, 256>>>(emb, A, W, vocab);
    gemm_hmma<<<dim3(NPAD / BN, MROWS / BM), 512, SM_TOTAL>>>(V, bvec, vocab);

    // join: recurrence needs the full table (GEMM cols + tail cols)
    cudaStreamWaitEvent(0, evJoin, 0);
    recurrence_kernel<<<(B + WPB - 1) / WPB, WPB * 32>>>(words, outW, outb, out, B);
}

// round 15
// speedup vs baseline: 1.0720x; 1.0720x over previous
#include <cuda_runtime.h>
#include <cuda_fp16.h>
#include <cstdint>
#include <math.h>

#define S_LEN  128
#define D_DIM  25
#define NCLS   5
#define E_DIM  301
#define KSEG   320                 // padded K per segment (301 -> 320)
#define MROWS  50048               // vocab padded to 128
#define NPAD   640                 // GEMM covers table cols [0,640): 5 full tiles
#define KBIG   960                 // 3 segments
#define PSTR   672                 // Ptable row stride (floats)
#define VOCAB_MAX 50000
#define BM     128
#define BN     128
#define BK     64
#define NCHUNK 15                  // 960/64
#define PLANE  ((size_t)MROWS * KSEG)
#define RSCALE 2048.0f             // residual-plane scale (2^11)
#define BBLK   800                 // prep blocks doing the B split (640*320/256)

// Segment order (correction first, main last):
//   chunks 0-4:   a0   x b1'   (B offset 0)    -> acc (at 2048x)
//   chunks 5-9:   a1'  x b0    (B offset 320)  -> acc (at 2048x)
//   [acc *= 1/2048]
//   chunks 10-14: a0   x b0    (B offset 640)  -> acc
// Table cols 640-649 (linear part, W cols 15-24): fp32 exact, fused into prep.

// ---------------- device globals (no runtime alloc allowed) ----------------
__device__ __align__(16) float  g_Ptable[(size_t)VOCAB_MAX * PSTR];
__device__ __align__(16) __half g_Ah[2 * PLANE];                // planes: a0, a1*2048
__device__ __align__(16) __half g_Bh[(size_t)NPAD * KBIG];      // rows: [b1*2048 | b0 | b0]

// ---------------- helpers ----------------
__device__ __forceinline__ uint32_t smem_u32(const void* p) {
    uint32_t a;
    asm("{ .reg .u64 t; cvta.to.shared.u64 t, %1; cvt.u32.u64 %0, t; }" : "=r"(a) : "l"(p));
    return a;
}
// 16B-granular xor swizzle for 128B rows
#define SWZ(row, cg) ((((uint32_t)(row)) << 7) + ((((cg) ^ ((row) & 7))) << 4))

#define CP16(dst, src) asm volatile("cp.async.cg.shared.global [%0], [%1], 16;" :: "r"(dst), "l"(src))
#define CP_COMMIT()    asm volatile("cp.async.commit_group;" ::: "memory")
#define CP_WAIT1()     asm volatile("cp.async.wait_group 1;" ::: "memory")

#define LDSM4(r, a) asm volatile( \
    "ldmatrix.sync.aligned.m8n8.x4.shared.b16 {%0,%1,%2,%3}, [%4];" \
    : "=r"((r)[0]), "=r"((r)[1]), "=r"((r)[2]), "=r"((r)[3]) : "r"(a))

#define MMA16816(c, a, b0, b1) asm volatile( \
    "mma.sync.aligned.m16n8k16.row.col.f32.f16.f16.f32 " \
    "{%0,%1,%2,%3}, {%4,%5,%6,%7}, {%8,%9}, {%0,%1,%2,%3};" \
    : "+f"((c)[0]), "+f"((c)[1]), "+f"((c)[2]), "+f"((c)[3]) \
    : "r"((a)[0]), "r"((a)[1]), "r"((a)[2]), "r"((a)[3]), "r"(b0), "r"(b1))

// ---------------------------------------------------------------------------
// Fused prep (R12 version): blocks [0,BBLK) build B planes; blocks [BBLK,..)
// split emb rows into fp16 planes a0 / a1*2048 and compute table cols 640-649.
// ---------------------------------------------------------------------------
__global__ void __launch_bounds__(256)
prep_all(const float* __restrict__ emb, const float* __restrict__ A,
         const float* __restrict__ W, const float* __restrict__ bvec, int vocab)
{
    if (blockIdx.x < BBLK) {
        // ---- B split: rows [n][960]: [0,320): b1*2048, [320,640): b0, [640,960): b0
        int idx = blockIdx.x * 256 + threadIdx.x;
        if (idx >= NPAD * KSEG) return;
        int n = idx / KSEG, k = idx % KSEG;
        float v = 0.f;
        if (k < E_DIM) {
            if (n < 625) v = A[((size_t)(n / 25) * E_DIM + k) * 25 + (n % 25)];
            else         v = W[(size_t)k * 25 + (n - 625)];
        }
        __half b0 = __float2half_rn(v);
        float r = (v - __half2float(b0)) * RSCALE;
        __half* row = g_Bh + (size_t)n * KBIG;
        row[k]       = __float2half_rn(r);
        row[320 + k] = b0;
        row[640 + k] = b0;
        return;
    }

    // ---- A split + fp32 tail (one warp per vocab row) ----
    __shared__ float Wt[E_DIM][10];
    for (int i = threadIdx.x; i < E_DIM * 10; i += 256) {
        int e = i / 10, d = i % 10;
        Wt[e][d] = W[e * 25 + 15 + d];
    }
    __syncthreads();

    const int lane = threadIdx.x & 31;
    const int m = (blockIdx.x - BBLK) * 8 + (threadIdx.x >> 5);
    if (m >= MROWS) return;
    const bool live = (m < vocab);
    const float* xr = emb + (size_t)m * E_DIM;
    __half2* p0 = (__half2*)(g_Ah + (size_t)m * KSEG);
    __half2* p1 = (__half2*)(g_Ah + PLANE + (size_t)m * KSEG);

    float acc[10];
    #pragma unroll
    for (int d = 0; d < 10; ++d) acc[d] = 0.f;

    #pragma unroll
    for (int i = 0; i < 5; ++i) {
        const int h = lane + 32 * i;        // half2 index, e = 2h
        const int e = 2 * h;
        float x0 = (live && e     < E_DIM) ? xr[e]     : 0.f;
        float x1 = (live && e + 1 < E_DIM) ? xr[e + 1] : 0.f;
        __half a00 = __float2half_rn(x0);
        __half a01 = __float2half_rn(x1);
        float r0 = (x0 - __half2float(a00)) * RSCALE;
        float r1 = (x1 - __half2float(a01)) * RSCALE;
        p0[h] = __halves2half2(a00, a01);
        p1[h] = __halves2half2(__float2half_rn(r0), __float2half_rn(r1));
        if (e < E_DIM) {
            #pragma unroll
            for (int d = 0; d < 10; ++d) acc[d] = fmaf(x0, Wt[e][d], acc[d]);
        }
        if (e + 1 < E_DIM) {
            #pragma unroll
            for (int d = 0; d < 10; ++d) acc[d] = fmaf(x1, Wt[e + 1][d], acc[d]);
        }
    }
    #pragma unroll
    for (int d = 0; d < 10; ++d)
        #pragma unroll
        for (int o = 16; o; o >>= 1)
            acc[d] += __shfl_down_sync(0xffffffffu, acc[d], o);
    if (lane == 0 && live) {
        float* orow = g_Ptable + (size_t)m * PSTR;
        #pragma unroll
        for (int d = 0; d < 10; ++d) orow[640 + d] = acc[d] + bvec[15 + d];
    }
}

// ---------------------------------------------------------------------------
// HMMA GEMM: 512 threads, 16 warps (4m x 4n grid), warp tile 32x32,
// 2 CTAs/SM (8 warps/SMSP). SINGLE-BUFFERED fragments -> ~56 live regs,
// genuinely <= the 64-reg cap of launch_bounds(512,2): no spills.
// Latency hiding comes from warp count (R12 lesson), not per-warp prefetch.
// 3-stage cp.async multistage, single barrier per chunk.
// ---------------------------------------------------------------------------
#define SM_STAGE 32768
#define SM_ADDV  (3 * SM_STAGE)
#define SM_TOTAL (3 * SM_STAGE + 512)

__global__ void __launch_bounds__(512, 2)
gemm_hmma(const float* __restrict__ V, const float* __restrict__ bvec, int vocab)
{
    extern __shared__ __align__(128) char smem[];
    const uint32_t sbase = smem_u32(smem);
    float* addv = (float*)(smem + SM_ADDV);

    const int tid  = threadIdx.x;
    const int w    = tid >> 5, lane = tid & 31;
    const int m0   = blockIdx.y * BM;
    const int n0   = blockIdx.x * BN;

    if (tid < BN) {
        int n = n0 + tid;
        float a;
        if (n < 625) a = V[(n % 25) * 25 + (n / 25)];
        else         a = bvec[n - 625];
        addv[tid] = a;
    }

    // ---- cp.async mapping: 512 threads, each 2x16B in A and B per chunk
    const int lrow = tid >> 2;
    const int lcg0 = (tid & 3) * 2;
    const uint32_t swz0 = SWZ(lrow, lcg0), swz1 = SWZ(lrow, lcg0 + 1);
    const __half* a_base = g_Ah + (size_t)(m0 + lrow) * KSEG + lcg0 * 8;
    const __half* b_base = g_Bh + (size_t)(n0 + lrow) * KBIG + lcg0 * 8;

    auto load_chunk = [&](int c, int st) {
        const int koff = (c % 5) * BK;
        const __half* asrc = a_base + ((c >= 5 && c < 10) ? PLANE : 0) + koff;
        const __half* bsrc = b_base + ((c < 5) ? 0 : ((c < 10) ? 320 : 640)) + koff;
        const uint32_t abase = sbase + st * SM_STAGE;
        const uint32_t bbase = abase + 16384;
        CP16(abase + swz0, asrc);
        CP16(abase + swz1, asrc + 8);
        CP16(bbase + swz0, bsrc);
        CP16(bbase + swz1, bsrc + 8);
    };

    float acc[2][4][4];
    #pragma unroll
    for (int mi = 0; mi < 2; ++mi)
        #pragma unroll
        for (int nj = 0; nj < 4; ++nj)
            #pragma unroll
            for (int q = 0; q < 4; ++q) acc[mi][nj][q] = 0.f;

    const int rowa = (w & 3) * 32 + (lane & 15);
    const int rowb = (w >> 2) * 32 + (lane & 15);
    const int cgl  = lane >> 4;

    load_chunk(0, 0); CP_COMMIT();
    load_chunk(1, 1); CP_COMMIT();

    #pragma unroll 3
    for (int c = 0; c < NCHUNK; ++c) {
        const int st = c % 3;
        CP_WAIT1();                     // group c complete (c+1 may be in flight)
        __syncthreads();                // all warps done reading stage (c+2)%3
        if (c + 2 < NCHUNK) {           // issue loads early, overlap with compute
            load_chunk(c + 2, (c + 2) % 3);
            CP_COMMIT();
        }
        if (c == 10) {
            const float inv = 1.0f / RSCALE;
            #pragma unroll
            for (int mi = 0; mi < 2; ++mi)
                #pragma unroll
                for (int nj = 0; nj < 4; ++nj)
                    #pragma unroll
                    for (int q = 0; q < 4; ++q) acc[mi][nj][q] *= inv;
        }
        const uint32_t abase = sbase + st * SM_STAGE;
        const uint32_t bbase = abase + 16384;

        #pragma unroll
        for (int kt = 0; kt < 4; ++kt) {
            uint32_t af[2][4], bf[2][4];
            const int cg = 2 * kt + cgl;
            LDSM4(af[0], abase + SWZ(rowa,      cg));
            LDSM4(af[1], abase + SWZ(rowa + 16, cg));
            LDSM4(bf[0], bbase + SWZ(rowb,      cg));
            LDSM4(bf[1], bbase + SWZ(rowb + 16, cg));
            #pragma unroll
            for (int mi = 0; mi < 2; ++mi)
                #pragma unroll
                for (int n8 = 0; n8 < 4; ++n8)
                    MMA16816(acc[mi][n8], af[mi],
                             bf[n8 >> 1][n8 & 1], bf[n8 >> 1][2 + (n8 & 1)]);
        }
    }

    // ---- epilogue: add fold values, store float2 pairs ----
    #pragma unroll
    for (int mi = 0; mi < 2; ++mi) {
        const int r0 = m0 + (w & 3) * 32 + mi * 16 + (lane >> 2);
        #pragma unroll
        for (int n8 = 0; n8 < 4; ++n8) {
            const int ln = (w >> 2) * 32 + n8 * 8 + (lane & 3) * 2;
            const int n  = n0 + ln;
            const float a0 = addv[ln], a1 = addv[ln + 1];
            if (r0 < vocab) {
                float2 v; v.x = acc[mi][n8][0] + a0; v.y = acc[mi][n8][1] + a1;
                *(float2*)(g_Ptable + (size_t)r0 * PSTR + n) = v;
            }
            if (r0 + 8 < vocab) {
                float2 v; v.x = acc[mi][n8][2] + a0; v.y = acc[mi][n8][3] + a1;
                *(float2*)(g_Ptable + (size_t)(r0 + 8) * PSTR + n) = v;
            }
        }
    }
}

// ---------------------------------------------------------------------------
// Recurrence (74us, LTS-bound floor): warp per batch element,
// cp.async 3-buffer pipeline. h_new = tanh(c + P h); fused sigmoid head.
// ---------------------------------------------------------------------------
#define WPB 4
__global__ void __launch_bounds__(128)
recurrence_kernel(const int* __restrict__ words,
                  const float* __restrict__ outW,
                  const float* __restrict__ outb,
                  float* __restrict__ out,
                  int B)
{
    __shared__ __align__(16) float Pbuf[WPB][3][656];
    __shared__ float hs[WPB][32];

    const int lane = threadIdx.x & 31;
    const int w    = threadIdx.x >> 5;
    const int b    = blockIdx.x * WPB + w;
    if (b >= B) return;   // uniform per warp

    const int* wrow = words + (size_t)b * S_LEN;
    float* hb = hs[w];
    hb[lane] = (lane == D_DIM - 1) ? 1.f : 0.f;

    auto issue = [&](int t, int s) {
        const char* src = (const char*)(g_Ptable + (size_t)wrow[t] * PSTR);
        const uint32_t dst = smem_u32(&Pbuf[w][s][0]);
        #pragma unroll
        for (int i = 0; i < 6; ++i) {
            int q = lane + 32 * i;
            if (q < 164) CP16(dst + q * 16, src + q * 16);
        }
    };

    issue(0, 0); CP_COMMIT();
    issue(1, 1); CP_COMMIT();

    for (int t = 0; t < S_LEN; ++t) {
        CP_WAIT1();
        __syncwarp();
        const float* pc = Pbuf[w][t % 3];
        float hn = 0.f;
        if (lane < D_DIM) {
            float acc = pc[625 + lane];
            const float* prow = pc + lane * D_DIM;
            #pragma unroll
            for (int j = 0; j < D_DIM; ++j)
                acc = fmaf(prow[j], hb[j], acc);
            hn = tanhf(acc);
        }
        __syncwarp();
        if (lane < D_DIM) hb[lane] = hn;
        __syncwarp();
        if (t + 2 < S_LEN) issue(t + 2, (t + 2) % 3);
        CP_COMMIT();
    }

    if (lane < NCLS) {
        float acc = outb[lane];
        #pragma unroll
        for (int i = 0; i < D_DIM; ++i)
            acc = fmaf(outW[lane * D_DIM + i], hb[i], acc);
        out[(size_t)b * NCLS + lane] = 1.f / (1.f + expf(-acc));
    }
}

// ---------------------------------------------------------------------------
extern "C" void kernel_launch(void* const* d_in, const int* in_sizes, int n_in,
                              void* d_out, int out_size)
{
    // inputs: words, [batch_size], emb_table, A, W, V, b, out_W, out_b
    const int o = (n_in >= 9) ? 1 : 0;
    const int*   words = (const int*)  d_in[0];
    const float* emb   = (const float*)d_in[1 + o];
    const float* A     = (const float*)d_in[2 + o];
    const float* W     = (const float*)d_in[3 + o];
    const float* V     = (const float*)d_in[4 + o];
    const float* bvec  = (const float*)d_in[5 + o];
    const float* outW  = (const float*)d_in[6 + o];
    const float* outb  = (const float*)d_in[7 + o];
    float* out = (float*)d_out;

    const int B = in_sizes[0] / S_LEN;
    int vocab   = in_sizes[1 + o] / E_DIM;
    if (vocab > VOCAB_MAX) vocab = VOCAB_MAX;

    // fused prep: B split + A split + fp32 tail
    prep_all<<<BBLK + MROWS / 8, 256>>>(emb, A, W, bvec, vocab);

    // tensor-core (HMMA) GEMM -> table cols [0,640)
    static bool cfg = false;
    if (!cfg) {
        cudaFuncSetAttribute(gemm_hmma, cudaFuncAttributeMaxDynamicSharedMemorySize, SM_TOTAL);
        cfg = true;
    }
    gemm_hmma<<<dim3(NPAD / BN, MROWS / BM), 512, SM_TOTAL>>>(V, bvec, vocab);

    // recurrence + head
    recurrence_kernel<<<(B + WPB - 1) / WPB, WPB * 32>>>(words, outW, outb, out, B);
}

// round 16
// speedup vs baseline: 1.1292x; 1.0534x over previous
#include <cuda_runtime.h>
#include <cuda_fp16.h>
#include <cstdint>
#include <math.h>

#define S_LEN  128
#define D_DIM  25
#define NCLS   5
#define E_DIM  301
#define KSEG   320                 // padded K per segment (301 -> 320)
#define MROWS  50048               // vocab padded to 128
#define NPAD   640                 // GEMM covers table cols [0,640): 5 full tiles
#define KBIG   960                 // 3 segments
#define PSTR   672                 // Ptable row stride (floats)
#define VOCAB_MAX 50000
#define BM     128
#define BN     128
#define BK     64
#define NCHUNK 15                  // 960/64
#define PLANE  ((size_t)MROWS * KSEG)
#define RSCALE 2048.0f             // residual-plane scale (2^11)
#define BBLK   800                 // prep blocks doing the B split (640*320/256)

// Segment order (correction first, main last):
//   chunks 0-4:   a0   x b1'   (B offset 0)    -> acc (at 2048x)
//   chunks 5-9:   a1'  x b0    (B offset 320)  -> acc (at 2048x)
//   [acc *= 1/2048]
//   chunks 10-14: a0   x b0    (B offset 640)  -> acc
// Table cols 640-649 (linear part, W cols 15-24): fp32 exact, fused into prep.

// ---------------- device globals (no runtime alloc allowed) ----------------
__device__ __align__(16) float  g_Ptable[(size_t)VOCAB_MAX * PSTR];
__device__ __align__(16) __half g_Ah[2 * PLANE];                // planes: a0, a1*2048
__device__ __align__(16) __half g_Bh[(size_t)NPAD * KBIG];      // rows: [b1*2048 | b0 | b0]

// ---------------- helpers ----------------
__device__ __forceinline__ uint32_t smem_u32(const void* p) {
    uint32_t a;
    asm("{ .reg .u64 t; cvta.to.shared.u64 t, %1; cvt.u32.u64 %0, t; }" : "=r"(a) : "l"(p));
    return a;
}
// 16B-granular xor swizzle for 128B rows
#define SWZ(row, cg) ((((uint32_t)(row)) << 7) + ((((cg) ^ ((row) & 7))) << 4))

#define CP16(dst, src) asm volatile("cp.async.cg.shared.global [%0], [%1], 16;" :: "r"(dst), "l"(src))
#define CP_COMMIT()    asm volatile("cp.async.commit_group;" ::: "memory")
#define CP_WAIT1()     asm volatile("cp.async.wait_group 1;" ::: "memory")

#define LDSM4(r, a) asm volatile( \
    "ldmatrix.sync.aligned.m8n8.x4.shared.b16 {%0,%1,%2,%3}, [%4];" \
    : "=r"((r)[0]), "=r"((r)[1]), "=r"((r)[2]), "=r"((r)[3]) : "r"(a))

#define MMA16816(c, a, b0, b1) asm volatile( \
    "mma.sync.aligned.m16n8k16.row.col.f32.f16.f16.f32 " \
    "{%0,%1,%2,%3}, {%4,%5,%6,%7}, {%8,%9}, {%0,%1,%2,%3};" \
    : "+f"((c)[0]), "+f"((c)[1]), "+f"((c)[2]), "+f"((c)[3]) \
    : "r"((a)[0]), "r"((a)[1]), "r"((a)[2]), "r"((a)[3]), "r"(b0), "r"(b1))

// ---------------------------------------------------------------------------
// Fused prep: blocks [0,BBLK) build B planes; blocks [BBLK,..) split emb rows
// into fp16 planes a0 / a1*2048 (packed converts) and table cols 640-649.
// ---------------------------------------------------------------------------
__global__ void __launch_bounds__(256)
prep_all(const float* __restrict__ emb, const float* __restrict__ A,
         const float* __restrict__ W, const float* __restrict__ bvec, int vocab)
{
    if (blockIdx.x < BBLK) {
        // ---- B split: rows [n][960]: [0,320): b1*2048, [320,640): b0, [640,960): b0
        int idx = blockIdx.x * 256 + threadIdx.x;
        if (idx >= NPAD * KSEG) return;
        int n = idx / KSEG, k = idx % KSEG;
        float v = 0.f;
        if (k < E_DIM) {
            if (n < 625) v = A[((size_t)(n / 25) * E_DIM + k) * 25 + (n % 25)];
            else         v = W[(size_t)k * 25 + (n - 625)];
        }
        __half b0 = __float2half_rn(v);
        float r = (v - __half2float(b0)) * RSCALE;
        __half* row = g_Bh + (size_t)n * KBIG;
        row[k]       = __float2half_rn(r);
        row[320 + k] = b0;
        row[640 + k] = b0;
        return;
    }

    // ---- A split + fp32 tail (one warp per vocab row) ----
    __shared__ float Wt[E_DIM][10];
    for (int i = threadIdx.x; i < E_DIM * 10; i += 256) {
        int e = i / 10, d = i % 10;
        Wt[e][d] = W[e * 25 + 15 + d];
    }
    __syncthreads();

    const int lane = threadIdx.x & 31;
    const int m = (blockIdx.x - BBLK) * 8 + (threadIdx.x >> 5);
    if (m >= MROWS) return;
    const bool live = (m < vocab);
    const float* xr = emb + (size_t)m * E_DIM;
    __half2* p0 = (__half2*)(g_Ah + (size_t)m * KSEG);
    __half2* p1 = (__half2*)(g_Ah + PLANE + (size_t)m * KSEG);

    float acc[10];
    #pragma unroll
    for (int d = 0; d < 10; ++d) acc[d] = 0.f;

    #pragma unroll
    for (int i = 0; i < 5; ++i) {
        const int h = lane + 32 * i;        // half2 index, e = 2h
        const int e = 2 * h;
        float x0 = (live && e     < E_DIM) ? xr[e]     : 0.f;
        float x1 = (live && e + 1 < E_DIM) ? xr[e + 1] : 0.f;
        // packed convert: one F2FP for the pair
        __half2 a01 = __float22half2_rn(make_float2(x0, x1));
        float2 back = __half22float2(a01);
        __half2 r01 = __float22half2_rn(
            make_float2((x0 - back.x) * RSCALE, (x1 - back.y) * RSCALE));
        p0[h] = a01;
        p1[h] = r01;
        if (e < E_DIM) {
            #pragma unroll
            for (int d = 0; d < 10; ++d) acc[d] = fmaf(x0, Wt[e][d], acc[d]);
        }
        if (e + 1 < E_DIM) {
            #pragma unroll
            for (int d = 0; d < 10; ++d) acc[d] = fmaf(x1, Wt[e + 1][d], acc[d]);
        }
    }
    #pragma unroll
    for (int d = 0; d < 10; ++d)
        #pragma unroll
        for (int o = 16; o; o >>= 1)
            acc[d] += __shfl_down_sync(0xffffffffu, acc[d], o);
    if (lane == 0 && live) {
        float* orow = g_Ptable + (size_t)m * PSTR;
        #pragma unroll
        for (int d = 0; d < 10; ++d) orow[640 + d] = acc[d] + bvec[15 + d];
    }
}

// ---------------------------------------------------------------------------
// HMMA GEMM: 512 threads, 16 warps (4m x 4n grid), warp tile 32x32,
// 2 CTAs/SM (8 warps/SMSP). Single-buffered fragments. 3-stage cp.async
// multistage, single barrier per chunk. FULLY UNROLLED chunk loop:
// all stage/segment/koff math constant-folds; no per-chunk branches.
// ---------------------------------------------------------------------------
#define SM_STAGE 32768
#define SM_ADDV  (3 * SM_STAGE)
#define SM_TOTAL (3 * SM_STAGE + 512)

__global__ void __launch_bounds__(512, 2)
gemm_hmma(const float* __restrict__ V, const float* __restrict__ bvec, int vocab)
{
    extern __shared__ __align__(128) char smem[];
    const uint32_t sbase = smem_u32(smem);
    float* addv = (float*)(smem + SM_ADDV);

    const int tid  = threadIdx.x;
    const int w    = tid >> 5, lane = tid & 31;
    const int m0   = blockIdx.y * BM;
    const int n0   = blockIdx.x * BN;

    if (tid < BN) {
        int n = n0 + tid;
        float a;
        if (n < 625) a = V[(n % 25) * 25 + (n / 25)];
        else         a = bvec[n - 625];
        addv[tid] = a;
    }

    // ---- cp.async mapping: 512 threads, each 2x16B in A and B per chunk
    const int lrow = tid >> 2;
    const int lcg0 = (tid & 3) * 2;
    const uint32_t swz0 = SWZ(lrow, lcg0), swz1 = SWZ(lrow, lcg0 + 1);
    const __half* a_base = g_Ah + (size_t)(m0 + lrow) * KSEG + lcg0 * 8;
    const __half* b_base = g_Bh + (size_t)(n0 + lrow) * KBIG + lcg0 * 8;

    auto load_chunk = [&](int c, int st) {
        const int koff = (c % 5) * BK;
        const __half* asrc = a_base + ((c >= 5 && c < 10) ? PLANE : 0) + koff;
        const __half* bsrc = b_base + ((c < 5) ? 0 : ((c < 10) ? 320 : 640)) + koff;
        const uint32_t abase = sbase + st * SM_STAGE;
        const uint32_t bbase = abase + 16384;
        CP16(abase + swz0, asrc);
        CP16(abase + swz1, asrc + 8);
        CP16(bbase + swz0, bsrc);
        CP16(bbase + swz1, bsrc + 8);
    };

    float acc[2][4][4];
    #pragma unroll
    for (int mi = 0; mi < 2; ++mi)
        #pragma unroll
        for (int nj = 0; nj < 4; ++nj)
            #pragma unroll
            for (int q = 0; q < 4; ++q) acc[mi][nj][q] = 0.f;

    const int rowa = (w & 3) * 32 + (lane & 15);
    const int rowb = (w >> 2) * 32 + (lane & 15);
    const int cgl  = lane >> 4;

    load_chunk(0, 0); CP_COMMIT();
    load_chunk(1, 1); CP_COMMIT();

    #pragma unroll
    for (int c = 0; c < NCHUNK; ++c) {     // FULL unroll: c is compile-time
        const int st = c % 3;
        CP_WAIT1();                     // group c complete (c+1 may be in flight)
        __syncthreads();                // all warps done reading stage (c+2)%3
        if (c + 2 < NCHUNK) {           // issue loads early, overlap with compute
            load_chunk(c + 2, (c + 2) % 3);
            CP_COMMIT();
        }
        if (c == 10) {
            const float inv = 1.0f / RSCALE;
            #pragma unroll
            for (int mi = 0; mi < 2; ++mi)
                #pragma unroll
                for (int nj = 0; nj < 4; ++nj)
                    #pragma unroll
                    for (int q = 0; q < 4; ++q) acc[mi][nj][q] *= inv;
        }
        const uint32_t abase = sbase + st * SM_STAGE;
        const uint32_t bbase = abase + 16384;

        #pragma unroll
        for (int kt = 0; kt < 4; ++kt) {
            uint32_t af[2][4], bf[2][4];
            const int cg = 2 * kt + cgl;
            LDSM4(af[0], abase + SWZ(rowa,      cg));
            LDSM4(af[1], abase + SWZ(rowa + 16, cg));
            LDSM4(bf[0], bbase + SWZ(rowb,      cg));
            LDSM4(bf[1], bbase + SWZ(rowb + 16, cg));
            #pragma unroll
            for (int mi = 0; mi < 2; ++mi)
                #pragma unroll
                for (int n8 = 0; n8 < 4; ++n8)
                    MMA16816(acc[mi][n8], af[mi],
                             bf[n8 >> 1][n8 & 1], bf[n8 >> 1][2 + (n8 & 1)]);
        }
    }

    // ---- epilogue: add fold values, store float2 pairs ----
    #pragma unroll
    for (int mi = 0; mi < 2; ++mi) {
        const int r0 = m0 + (w & 3) * 32 + mi * 16 + (lane >> 2);
        #pragma unroll
        for (int n8 = 0; n8 < 4; ++n8) {
            const int ln = (w >> 2) * 32 + n8 * 8 + (lane & 3) * 2;
            const int n  = n0 + ln;
            const float a0 = addv[ln], a1 = addv[ln + 1];
            if (r0 < vocab) {
                float2 v; v.x = acc[mi][n8][0] + a0; v.y = acc[mi][n8][1] + a1;
                *(float2*)(g_Ptable + (size_t)r0 * PSTR + n) = v;
            }
            if (r0 + 8 < vocab) {
                float2 v; v.x = acc[mi][n8][2] + a0; v.y = acc[mi][n8][3] + a1;
                *(float2*)(g_Ptable + (size_t)(r0 + 8) * PSTR + n) = v;
            }
        }
    }
}

// ---------------------------------------------------------------------------
// Recurrence (74us, LTS-bound floor): warp per batch element,
// cp.async 3-buffer pipeline. h_new = tanh(c + P h); fused sigmoid head.
// ---------------------------------------------------------------------------
#define WPB 4
__global__ void __launch_bounds__(128)
recurrence_kernel(const int* __restrict__ words,
                  const float* __restrict__ outW,
                  const float* __restrict__ outb,
                  float* __restrict__ out,
                  int B)
{
    __shared__ __align__(16) float Pbuf[WPB][3][656];
    __shared__ float hs[WPB][32];

    const int lane = threadIdx.x & 31;
    const int w    = threadIdx.x >> 5;
    const int b    = blockIdx.x * WPB + w;
    if (b >= B) return;   // uniform per warp

    const int* wrow = words + (size_t)b * S_LEN;
    float* hb = hs[w];
    hb[lane] = (lane == D_DIM - 1) ? 1.f : 0.f;

    auto issue = [&](int t, int s) {
        const char* src = (const char*)(g_Ptable + (size_t)wrow[t] * PSTR);
        const uint32_t dst = smem_u32(&Pbuf[w][s][0]);
        #pragma unroll
        for (int i = 0; i < 6; ++i) {
            int q = lane + 32 * i;
            if (q < 164) CP16(dst + q * 16, src + q * 16);
        }
    };

    issue(0, 0); CP_COMMIT();
    issue(1, 1); CP_COMMIT();

    for (int t = 0; t < S_LEN; ++t) {
        CP_WAIT1();
        __syncwarp();
        const float* pc = Pbuf[w][t % 3];
        float hn = 0.f;
        if (lane < D_DIM) {
            float acc = pc[625 + lane];
            const float* prow = pc + lane * D_DIM;
            #pragma unroll
            for (int j = 0; j < D_DIM; ++j)
                acc = fmaf(prow[j], hb[j], acc);
            hn = tanhf(acc);
        }
        __syncwarp();
        if (lane < D_DIM) hb[lane] = hn;
        __syncwarp();
        if (t + 2 < S_LEN) issue(t + 2, (t + 2) % 3);
        CP_COMMIT();
    }

    if (lane < NCLS) {
        float acc = outb[lane];
        #pragma unroll
        for (int i = 0; i < D_DIM; ++i)
            acc = fmaf(outW[lane * D_DIM + i], hb[i], acc);
        out[(size_t)b * NCLS + lane] = 1.f / (1.f + expf(-acc));
    }
}

// ---------------------------------------------------------------------------
extern "C" void kernel_launch(void* const* d_in, const int* in_sizes, int n_in,
                              void* d_out, int out_size)
{
    // inputs: words, [batch_size], emb_table, A, W, V, b, out_W, out_b
    const int o = (n_in >= 9) ? 1 : 0;
    const int*   words = (const int*)  d_in[0];
    const float* emb   = (const float*)d_in[1 + o];
    const float* A     = (const float*)d_in[2 + o];
    const float* W     = (const float*)d_in[3 + o];
    const float* V     = (const float*)d_in[4 + o];
    const float* bvec  = (const float*)d_in[5 + o];
    const float* outW  = (const float*)d_in[6 + o];
    const float* outb  = (const float*)d_in[7 + o];
    float* out = (float*)d_out;

    const int B = in_sizes[0] / S_LEN;
    int vocab   = in_sizes[1 + o] / E_DIM;
    if (vocab > VOCAB_MAX) vocab = VOCAB_MAX;

    // fused prep: B split + A split + fp32 tail
    prep_all<<<BBLK + MROWS / 8, 256>>>(emb, A, W, bvec, vocab);

    // tensor-core (HMMA) GEMM -> table cols [0,640)
    static bool cfg = false;
    if (!cfg) {
        cudaFuncSetAttribute(gemm_hmma, cudaFuncAttributeMaxDynamicSharedMemorySize, SM_TOTAL);
        cfg = true;
    }
    gemm_hmma<<<dim3(NPAD / BN, MROWS / BM), 512, SM_TOTAL>>>(V, bvec, vocab);

    // recurrence + head
    recurrence_kernel<<<(B + WPB - 1) / WPB, WPB * 32>>>(words, outW, outb, out, B);
}